// round 3
// baseline (speedup 1.0000x reference)
#include <cuda_runtime.h>

// ---------------- problem constants ----------------
#define NN    100000
#define EE    1600000
#define HIDD  128
#define HEADS 8
#define CC    16
#define LAYERS 3

// ---------------- device scratch (no allocs allowed) ----------------
__device__ float g_h [(size_t)NN * HIDD];   // node features (layer input / output)
__device__ float g_h2[(size_t)NN * HIDD];   // h @ W (per-head features)
__device__ float g_y [(size_t)NN * HIDD];   // GAT output + conv bias (pre-BN)
__device__ float g_alsrc[NN * HEADS];
__device__ float g_aldst[NN * HEADS];
__device__ int   g_rowptr[NN + 1];
__device__ int   g_fill[NN];                // reused: counts -> fill cursors
__device__ int   g_col[EE];
__device__ int   g_bsums[256];
__device__ float g_bnsum[HIDD];
__device__ float g_bnsq[HIDD];
__device__ float g_scale[HIDD];
__device__ float g_shift[HIDD];

// ---------------- small helpers ----------------
__device__ __forceinline__ float lrelu02(float x) { return x > 0.f ? x : 0.2f * x; }
__device__ __forceinline__ float eluf(float x)    { return x > 0.f ? x : expm1f(x); }

// ---------------- CSR build ----------------
__global__ void zero_int_kernel(int* p, int n) {
    int t = blockIdx.x * blockDim.x + threadIdx.x;
    if (t < n) p[t] = 0;
}

__global__ void hist_kernel(const int* __restrict__ dst, int* __restrict__ cnt, int E) {
    int t = blockIdx.x * blockDim.x + threadIdx.x;
    if (t < E) atomicAdd(&cnt[dst[t]], 1);
}

// per-block exclusive scan of 1024 elements; bsums[b] = block total
__global__ void scan_block_kernel(const int* __restrict__ in, int* __restrict__ out,
                                  int* __restrict__ bsums, int n) {
    __shared__ int s[1024];
    int tid = threadIdx.x;
    int gid = blockIdx.x * 1024 + tid;
    s[tid] = (gid < n) ? in[gid] : 0;
    __syncthreads();
    #pragma unroll
    for (int off = 1; off < 1024; off <<= 1) {
        int v = (tid >= off) ? s[tid - off] : 0;
        __syncthreads();
        s[tid] += v;
        __syncthreads();
    }
    if (gid < n) out[gid] = (tid == 0) ? 0 : s[tid - 1];
    if (tid == 1023) bsums[blockIdx.x] = s[1023];
}

// single-block exclusive scan of block sums (n <= 128)
__global__ void scan_small_kernel(int* data, int n) {
    __shared__ int s[128];
    int tid = threadIdx.x;
    s[tid] = (tid < n) ? data[tid] : 0;
    __syncthreads();
    #pragma unroll
    for (int off = 1; off < 128; off <<= 1) {
        int v = (tid >= off) ? s[tid - off] : 0;
        __syncthreads();
        s[tid] += v;
        __syncthreads();
    }
    if (tid < n) data[tid] = (tid == 0) ? 0 : s[tid - 1];
}

__global__ void scan_add_kernel(int* __restrict__ rowptr, int* __restrict__ fill,
                                const int* __restrict__ bsums, int n, int total) {
    int gid = blockIdx.x * 1024 + threadIdx.x;
    if (gid < n) {
        int v = rowptr[gid] + bsums[blockIdx.x];
        rowptr[gid] = v;
        fill[gid]   = v;
    }
    if (gid == 0) rowptr[n] = total;
}

__global__ void scatter_kernel(const int* __restrict__ src, const int* __restrict__ dst,
                               int* __restrict__ fill, int* __restrict__ col, int E) {
    int t = blockIdx.x * blockDim.x + threadIdx.x;
    if (t < E) {
        int d = dst[t];
        int p = atomicAdd(&fill[d], 1);
        col[p] = src[t];
    }
}

// ---------------- SGEMM: C[M,128] = A[M,K] @ B[K,128] (+ bias, elu) ----------------
template<int K, bool BIAS_ELU>
__global__ __launch_bounds__(256)
void sgemm_kernel(const float* __restrict__ A, const float* __restrict__ B,
                  const float* __restrict__ bias, float* __restrict__ C, int M) {
    __shared__ float As[16][128];
    __shared__ float Bs[16][128];
    int tid  = threadIdx.x;
    int bm   = blockIdx.x * 128;
    int trow = (tid >> 4) * 8;
    int tcol = (tid & 15) * 8;
    float acc[8][8];
    #pragma unroll
    for (int i = 0; i < 8; i++)
        #pragma unroll
        for (int j = 0; j < 8; j++) acc[i][j] = 0.f;

    for (int kt = 0; kt < K; kt += 16) {
        // load A tile (128 x 16), transposed into As[k][m]
        #pragma unroll
        for (int t = 0; t < 2; t++) {
            int li  = tid + t * 256;        // 0..511
            int row = li >> 2;              // 0..127
            int c4  = (li & 3) * 4;         // 0,4,8,12
            float4 v = make_float4(0.f, 0.f, 0.f, 0.f);
            int gr = bm + row;
            if (gr < M) v = *(const float4*)(A + (size_t)gr * K + kt + c4);
            As[c4 + 0][row] = v.x;
            As[c4 + 1][row] = v.y;
            As[c4 + 2][row] = v.z;
            As[c4 + 3][row] = v.w;
        }
        // load B tile (16 x 128)
        #pragma unroll
        for (int t = 0; t < 2; t++) {
            int li  = tid + t * 256;
            int row = li >> 5;              // 0..15
            int c4  = (li & 31) * 4;        // 0..124
            *(float4*)(&Bs[row][c4]) = *(const float4*)(B + (size_t)(kt + row) * HIDD + c4);
        }
        __syncthreads();
        #pragma unroll
        for (int k = 0; k < 16; k++) {
            float a[8], b[8];
            *(float4*)(&a[0]) = *(const float4*)(&As[k][trow]);
            *(float4*)(&a[4]) = *(const float4*)(&As[k][trow + 4]);
            *(float4*)(&b[0]) = *(const float4*)(&Bs[k][tcol]);
            *(float4*)(&b[4]) = *(const float4*)(&Bs[k][tcol + 4]);
            #pragma unroll
            for (int i = 0; i < 8; i++)
                #pragma unroll
                for (int j = 0; j < 8; j++)
                    acc[i][j] += a[i] * b[j];
        }
        __syncthreads();
    }
    #pragma unroll
    for (int i = 0; i < 8; i++) {
        int gr = bm + trow + i;
        if (gr < M) {
            float o[8];
            #pragma unroll
            for (int j = 0; j < 8; j++) {
                float v = acc[i][j];
                if (BIAS_ELU) { v += bias[tcol + j]; v = eluf(v); }
                o[j] = v;
            }
            *(float4*)(C + (size_t)gr * HIDD + tcol)     = *(float4*)(&o[0]);
            *(float4*)(C + (size_t)gr * HIDD + tcol + 4) = *(float4*)(&o[4]);
        }
    }
}

// ---------------- attention logits: al[n,h] = <h2[n,h,:], att[h,:]> ----------------
__global__ void al_kernel(const float* __restrict__ h2, const float* __restrict__ att_s,
                          const float* __restrict__ att_d, float* __restrict__ alsrc,
                          float* __restrict__ aldst) {
    int t = blockIdx.x * blockDim.x + threadIdx.x;
    if (t >= NN * HEADS) return;
    int n = t >> 3, hd = t & 7;
    const float* hp = h2 + (size_t)n * HIDD + hd * CC;
    const float* as = att_s + hd * CC;
    const float* ad = att_d + hd * CC;
    float ss = 0.f, sd = 0.f;
    #pragma unroll
    for (int c = 0; c < CC; c++) {
        float v = hp[c];
        ss += v * as[c];
        sd += v * ad[c];
    }
    alsrc[t] = ss;
    aldst[t] = sd;
}

// ---------------- warp-per-node softmax aggregate (CSR, incl. self loop) ----------
__global__ __launch_bounds__(256)
void gat_agg_kernel(const float* __restrict__ h2, const float* __restrict__ alsrc,
                    const float* __restrict__ aldst, const int* __restrict__ rowptr,
                    const int* __restrict__ colidx, const float* __restrict__ convb,
                    float* __restrict__ y) {
    int node = (blockIdx.x * blockDim.x + threadIdx.x) >> 5;
    if (node >= NN) return;
    int lane = threadIdx.x & 31;
    int hd   = lane >> 2;                         // lane owns channels [4*lane, 4*lane+4)

    float adn   = aldst[node * HEADS + hd];
    float asn   = alsrc[node * HEADS + hd];
    float eself = lrelu02(asn + adn);
    float m     = eself;
    int s0 = rowptr[node], s1 = rowptr[node + 1];

    // pass 1: max
    #pragma unroll 4
    for (int i = s0; i < s1; i++) {
        int s = colidx[i];
        m = fmaxf(m, lrelu02(alsrc[s * HEADS + hd] + adn));
    }
    // pass 2: exp-sum + weighted aggregate
    float wself = __expf(eself - m);
    float denom = wself;
    float4 v = *(const float4*)(h2 + (size_t)node * HIDD + lane * 4);
    float4 acc = make_float4(wself * v.x, wself * v.y, wself * v.z, wself * v.w);
    #pragma unroll 4
    for (int i = s0; i < s1; i++) {
        int s = colidx[i];
        float wgt = __expf(lrelu02(alsrc[s * HEADS + hd] + adn) - m);
        denom += wgt;
        float4 u = *(const float4*)(h2 + (size_t)s * HIDD + lane * 4);
        acc.x += wgt * u.x; acc.y += wgt * u.y;
        acc.z += wgt * u.z; acc.w += wgt * u.w;
    }
    float inv = 1.f / (denom + 1e-16f);
    const float4 cb = *(const float4*)(convb + lane * 4);
    float4 o = make_float4(acc.x * inv + cb.x, acc.y * inv + cb.y,
                           acc.z * inv + cb.z, acc.w * inv + cb.w);
    *(float4*)(y + (size_t)node * HIDD + lane * 4) = o;
}

// ---------------- batchnorm ----------------
__global__ void bn_zero_kernel(float* bnsum, float* bnsq) {
    int t = threadIdx.x;
    bnsum[t] = 0.f;
    bnsq[t]  = 0.f;
}

__global__ void bn_reduce_kernel(const float* __restrict__ y, float* bnsum, float* bnsq) {
    int ch = threadIdx.x;   // 128 threads = 128 channels
    float s = 0.f, q = 0.f;
    for (int r = blockIdx.x; r < NN; r += gridDim.x) {
        float v = y[(size_t)r * HIDD + ch];
        s += v;
        q += v * v;
    }
    atomicAdd(&bnsum[ch], s);
    atomicAdd(&bnsq[ch], q);
}

__global__ void bn_final_kernel(const float* bnsum, const float* bnsq,
                                const float* __restrict__ g, const float* __restrict__ b,
                                float* scale, float* shift) {
    int ch = threadIdx.x;
    float mu  = bnsum[ch] * (1.f / NN);
    float var = bnsq[ch] * (1.f / NN) - mu * mu;
    float sc  = g[ch] * rsqrtf(var + 1e-5f);
    scale[ch] = sc;
    shift[ch] = b[ch] - mu * sc;
}

// h = elu(y * scale + shift) + h   (residual)
__global__ void bn_apply_kernel(const float* __restrict__ y, const float* __restrict__ scale,
                                const float* __restrict__ shift, float* __restrict__ h) {
    int t = blockIdx.x * blockDim.x + threadIdx.x;
    if (t < NN * HIDD) {
        int ch = t & 127;
        float v = fmaf(y[t], scale[ch], shift[ch]);
        h[t] = eluf(v) + h[t];
    }
}

// ---------------- final fc: out[n] = <h[n,:], w> + b ----------------
__global__ void fc_kernel(const float* __restrict__ h, const float* __restrict__ w,
                          const float* __restrict__ b, float* __restrict__ out) {
    int gt = blockIdx.x * blockDim.x + threadIdx.x;
    int n = gt >> 5;
    if (n >= NN) return;
    int lane = gt & 31;
    float4 hv = *(const float4*)(h + (size_t)n * HIDD + lane * 4);
    float4 wv = *(const float4*)(w + lane * 4);
    float s = hv.x * wv.x + hv.y * wv.y + hv.z * wv.z + hv.w * wv.w;
    #pragma unroll
    for (int o = 16; o; o >>= 1) s += __shfl_xor_sync(0xffffffffu, s, o);
    if (lane == 0) out[n] = s + b[0];
}

// ---------------- launch ----------------
extern "C" void kernel_launch(void* const* d_in, const int* in_sizes, int n_in,
                              void* d_out, int out_size) {
    const float* x       = (const float*)d_in[0];
    const int*   ei      = (const int*)  d_in[1];
    const float* proj_w  = (const float*)d_in[2];
    const float* proj_b  = (const float*)d_in[3];
    const float* Wl      = (const float*)d_in[4];
    const float* att_src = (const float*)d_in[5];
    const float* att_dst = (const float*)d_in[6];
    const float* conv_b  = (const float*)d_in[7];
    const float* bn_g    = (const float*)d_in[8];
    const float* bn_b    = (const float*)d_in[9];
    const float* fc_w    = (const float*)d_in[10];
    const float* fc_b    = (const float*)d_in[11];
    float* out = (float*)d_out;

    int E = in_sizes[1] / 2;
    const int* srcA = ei;
    const int* dstA = ei + E;

    float *p_h, *p_h2, *p_y, *p_alsrc, *p_aldst, *p_bnsum, *p_bnsq, *p_scale, *p_shift;
    int *p_rowptr, *p_fill, *p_col, *p_bsums;
    cudaGetSymbolAddress((void**)&p_h,      g_h);
    cudaGetSymbolAddress((void**)&p_h2,     g_h2);
    cudaGetSymbolAddress((void**)&p_y,      g_y);
    cudaGetSymbolAddress((void**)&p_alsrc,  g_alsrc);
    cudaGetSymbolAddress((void**)&p_aldst,  g_aldst);
    cudaGetSymbolAddress((void**)&p_rowptr, g_rowptr);
    cudaGetSymbolAddress((void**)&p_fill,   g_fill);
    cudaGetSymbolAddress((void**)&p_col,    g_col);
    cudaGetSymbolAddress((void**)&p_bsums,  g_bsums);
    cudaGetSymbolAddress((void**)&p_bnsum,  g_bnsum);
    cudaGetSymbolAddress((void**)&p_bnsq,   g_bnsq);
    cudaGetSymbolAddress((void**)&p_scale,  g_scale);
    cudaGetSymbolAddress((void**)&p_shift,  g_shift);

    // ---- CSR build (dst-sorted) ----
    zero_int_kernel<<<(NN + 255) / 256, 256>>>(p_fill, NN);
    hist_kernel<<<(E + 255) / 256, 256>>>(dstA, p_fill, E);
    int nblk = (NN + 1023) / 1024;
    scan_block_kernel<<<nblk, 1024>>>(p_fill, p_rowptr, p_bsums, NN);
    scan_small_kernel<<<1, 128>>>(p_bsums, nblk);
    scan_add_kernel<<<nblk, 1024>>>(p_rowptr, p_fill, p_bsums, NN, E);
    scatter_kernel<<<(E + 255) / 256, 256>>>(srcA, dstA, p_fill, p_col, E);

    // ---- input projection + elu ----
    int mblk = (NN + 127) / 128;
    sgemm_kernel<256, true><<<mblk, 256>>>(x, proj_w, proj_b, p_h, NN);

    // ---- GAT layers ----
    for (int l = 0; l < LAYERS; l++) {
        sgemm_kernel<128, false><<<mblk, 256>>>(p_h, Wl + (size_t)l * HIDD * HIDD,
                                                nullptr, p_h2, NN);
        al_kernel<<<(NN * HEADS + 255) / 256, 256>>>(p_h2, att_src + l * HEADS * CC,
                                                     att_dst + l * HEADS * CC,
                                                     p_alsrc, p_aldst);
        gat_agg_kernel<<<(NN * 32 + 255) / 256, 256>>>(p_h2, p_alsrc, p_aldst,
                                                       p_rowptr, p_col,
                                                       conv_b + l * HIDD, p_y);
        bn_zero_kernel<<<1, 128>>>(p_bnsum, p_bnsq);
        bn_reduce_kernel<<<1024, 128>>>(p_y, p_bnsum, p_bnsq);
        bn_final_kernel<<<1, 128>>>(p_bnsum, p_bnsq, bn_g + l * HIDD, bn_b + l * HIDD,
                                    p_scale, p_shift);
        bn_apply_kernel<<<(NN * HIDD + 255) / 256, 256>>>(p_y, p_scale, p_shift, p_h);
    }

    // ---- final linear ----
    fc_kernel<<<(NN * 32 + 255) / 256, 256>>>(p_h, fc_w, fc_b, out);
}